// round 3
// baseline (speedup 1.0000x reference)
#include <cuda_runtime.h>
#include <math.h>

#define NN 5000
#define NL 20000
#define NP 50000

// ------------------------- device-global scratch -------------------------
__device__ __align__(16) float g_link[2][NL * 32];
__device__ __align__(16) float g_node[2][NN * 32];
__device__ __align__(16) float g_path[NP * 64];
__device__ __align__(16) float g_m[NL * 64];
__device__ __align__(16) float g_Lx[NL * 192];
__device__ __align__(16) float g_Nx[NN * 192];
__device__ __align__(16) float g_ker[(size_t)NL * 1024];
__device__ __align__(16) float g_wpack[12288];   // packed gru_wh
__device__ __align__(16) float g_b1pack[192];
__device__ __align__(16) float g_We[4096];       // fused edge MLP
__device__ __align__(16) float g_be[32];

// ------------------------------ helpers ----------------------------------
__device__ __forceinline__ float sigm(float x) {
    return __fdividef(1.0f, 1.0f + __expf(-x));
}
__device__ __forceinline__ float tanh_fast(float x) {
    float ax = fabsf(x);
    float e  = __expf(-2.0f * ax);
    float t  = __fdividef(1.0f - e, 1.0f + e);
    return copysignf(t, x);
}
__device__ __forceinline__ float selu_f(float x) {
    return x > 0.0f ? 1.0507009873554805f * x
                    : 1.7580993408473766f * (__expf(x) - 1.0f);
}
__device__ __forceinline__ void red4(float* a, float x, float y, float z, float w) {
    asm volatile("red.global.add.v4.f32 [%0], {%1,%2,%3,%4};"
                 :: "l"(a), "f"(x), "f"(y), "f"(z), "f"(w) : "memory");
}

// ----------------------------- prep kernels ------------------------------
// wpack[((i*16+jg)*3+g)*4+k] = wh[i*192 + g*64 + jg*4 + k]
__global__ void prep_gru_k(const float* __restrict__ wh, const float* __restrict__ b) {
    int idx = blockIdx.x * 256 + threadIdx.x;
    if (idx < 12288) {
        int k = idx & 3;
        int q = idx >> 2;
        int g = q % 3;
        int m2 = q / 3;
        int jg = m2 & 15;
        int i  = m2 >> 4;
        g_wpack[idx] = wh[i * 192 + g * 64 + jg * 4 + k];
    } else if (idx < 12480) {
        int r = idx - 12288;           // jg*12 + g*4 + k
        int k = r & 3;
        int g = (r >> 2) % 3;
        int jg = (r >> 2) / 3;
        g_b1pack[r] = b[192 + g * 64 + jg * 4 + k];
    }
}

__global__ void prep_edge_k(const float* __restrict__ w1, const float* __restrict__ b1,
                            const float* __restrict__ w2, const float* __restrict__ b2) {
    int idx = blockIdx.x * 256 + threadIdx.x;
    if (idx < 4096) {
        int c = idx >> 5, j = idx & 31;
        float acc = 0.0f;
        #pragma unroll
        for (int k = 0; k < 32; k++) acc += w1[c * 32 + k] * w2[k * 32 + j];
        g_We[idx] = acc;
    } else if (idx < 4096 + 32) {
        int j = idx - 4096;
        float acc = b2[j];
        #pragma unroll
        for (int k = 0; k < 32; k++) acc += b1[k] * w2[k * 32 + j];
        g_be[j] = acc;
    }
}

// ----------------------------- init kernels ------------------------------
__global__ void init_link_k(const float* __restrict__ li) {
    int idx = blockIdx.x * 256 + threadIdx.x;       // 640000
    int l = idx >> 5, c = idx & 31;
    g_link[0][idx] = (c == 0) ? li[l] : 0.0f;
}
__global__ void init_node_k(const float* __restrict__ ni) {
    int idx = blockIdx.x * 256 + threadIdx.x;       // 160000
    int n = idx >> 5, c = idx & 31;
    g_node[0][idx] = (c == 0) ? ni[n] : 0.0f;
}
__global__ void init_path_k(const float* __restrict__ pi) {
    int idx = blockIdx.x * 256 + threadIdx.x;       // 3200000
    int p = idx >> 6, c = idx & 63;
    float v = 0.0f;
    if (c == 0) v = pi[p];
    else if (c == 1) v = pi[NP + p];
    g_path[idx] = v;
}
__global__ void zero_m_k() {
    int idx = blockIdx.x * 256 + threadIdx.x;       // 320000 float4
    ((float4*)g_m)[idx] = make_float4(0.f, 0.f, 0.f, 0.f);
}
__global__ void zero_node_k(int which) {
    int idx = blockIdx.x * 256 + threadIdx.x;
    if (idx < 40000)
        ((float4*)g_node[which])[idx] = make_float4(0.f, 0.f, 0.f, 0.f);
}

// --------------------- Lx = link_state @ wx[0:32] + b0 -------------------
__global__ void __launch_bounds__(192) lx_kernel(const float* __restrict__ wx,
                                                 const float* __restrict__ b, int cur) {
    __shared__ float swx[6144];
    __shared__ float sls[8][33];
    int tid = threadIdx.x;
    for (int r = tid; r < 6144; r += 192) swx[r] = wx[r];
    for (int r = tid; r < 256; r += 192) {
        int l = r >> 5, c = r & 31;
        sls[l][c] = g_link[cur][(size_t)(blockIdx.x * 8 + l) * 32 + c];
    }
    __syncthreads();
    int j = tid;
    float bj = b[j];
    for (int l = 0; l < 8; l++) {
        float acc = bj;
        #pragma unroll
        for (int i = 0; i < 32; i++) acc += sls[l][i] * swx[i * 192 + j];
        g_Lx[(size_t)(blockIdx.x * 8 + l) * 192 + j] = acc;
    }
}

// --------------------- Nx = node_state @ wx[32:64] -----------------------
__global__ void __launch_bounds__(192) nx_kernel(const float* __restrict__ wx, int cur) {
    __shared__ float swx[6144];
    __shared__ float sns[8][33];
    int tid = threadIdx.x;
    for (int r = tid; r < 6144; r += 192) swx[r] = wx[6144 + r];
    for (int r = tid; r < 256; r += 192) {
        int n = r >> 5, c = r & 31;
        sns[n][c] = g_node[cur][(size_t)(blockIdx.x * 8 + n) * 32 + c];
    }
    __syncthreads();
    int j = tid;
    for (int n = 0; n < 8; n++) {
        float acc = 0.0f;
        #pragma unroll
        for (int i = 0; i < 32; i++) acc += sns[n][i] * swx[i * 192 + j];
        g_Nx[(size_t)(blockIdx.x * 8 + n) * 192 + j] = acc;
    }
}

// --------------------------- fused GRU scan ------------------------------
// block = 256 threads: pg = tid>>4 (16 path-groups of 4), jg = tid&15 (j-quads)
// smem: wpack 12288f | b1 192f | sgx 64*196f | h double-buffer 2*64*68f
#define GRU_SMEM_BYTES 134912
__global__ void __launch_bounds__(256, 1) gru_kernel(const int* __restrict__ l2p,
                                                     const int* __restrict__ n2p) {
    extern __shared__ float sm[];
    float4* wsm = (float4*)sm;               // 3072 quads
    float*  sb1 = sm + 12288;
    float*  sgx = sm + 12480;
    float4* sgx4 = (float4*)sgx;
    float*  shh = sm + 25024;

    int tid = threadIdx.x;
    int pg = tid >> 4, jg = tid & 15;
    int pbase = blockIdx.x * 64;

    const float4* wgl = (const float4*)g_wpack;
    #pragma unroll
    for (int r = 0; r < 12; r++) wsm[r * 256 + tid] = wgl[r * 256 + tid];
    if (tid < 192) sb1[tid] = g_b1pack[tid];

    // load h (path_state) into smem [i][p] layout, stride 68
    const float4* gp4 = (const float4*)g_path;
    #pragma unroll
    for (int r = 0; r < 4; r++) {
        int idx = r * 256 + tid;
        int p = idx >> 4, iq = idx & 15;
        int pglob = pbase + p; if (pglob >= NP) pglob = NP - 1;
        float4 v = gp4[(size_t)pglob * 16 + iq];
        shh[(iq * 4 + 0) * 68 + p] = v.x;
        shh[(iq * 4 + 1) * 68 + p] = v.y;
        shh[(iq * 4 + 2) * 68 + p] = v.z;
        shh[(iq * 4 + 3) * 68 + p] = v.w;
    }
    __syncthreads();

    float4 bq0 = ((float4*)sb1)[jg * 3 + 0];
    float4 bq1 = ((float4*)sb1)[jg * 3 + 1];
    float4 bq2 = ((float4*)sb1)[jg * 3 + 2];

    const float4* Lx4 = (const float4*)g_Lx;
    const float4* Nx4 = (const float4*)g_Nx;

    int hbuf = 0;
    for (int t = 0; t < 8; t++) {
        // stage gx = Lx[l] + Nx[n] (+b0 folded in Lx) for 64 paths
        #pragma unroll
        for (int r = 0; r < 12; r++) {
            int idx = r * 256 + tid;
            int p = idx / 48, q = idx % 48;
            int pglob = pbase + p; if (pglob >= NP) pglob = NP - 1;
            int e = pglob * 8 + t;
            int li = l2p[e], ni = n2p[e];
            float4 a4 = Lx4[(size_t)li * 48 + q];
            float4 b4 = Nx4[(size_t)ni * 48 + q];
            a4.x += b4.x; a4.y += b4.y; a4.z += b4.z; a4.w += b4.w;
            sgx4[p * 49 + q] = a4;
        }
        __syncthreads();

        float* shH  = shh + hbuf * 4352;
        float* shHn = shh + (hbuf ^ 1) * 4352;

        float a[4][12];
        #pragma unroll
        for (int pp = 0; pp < 4; pp++) {
            a[pp][0] = bq0.x; a[pp][1] = bq0.y; a[pp][2]  = bq0.z; a[pp][3]  = bq0.w;
            a[pp][4] = bq1.x; a[pp][5] = bq1.y; a[pp][6]  = bq1.z; a[pp][7]  = bq1.w;
            a[pp][8] = bq2.x; a[pp][9] = bq2.y; a[pp][10] = bq2.z; a[pp][11] = bq2.w;
        }

        #pragma unroll 8
        for (int i = 0; i < 64; i++) {
            float4 h4 = *(const float4*)(shH + i * 68 + pg * 4);
            float4 w0 = wsm[(i * 16 + jg) * 3 + 0];
            float4 w1 = wsm[(i * 16 + jg) * 3 + 1];
            float4 w2 = wsm[(i * 16 + jg) * 3 + 2];
            float hv[4] = {h4.x, h4.y, h4.z, h4.w};
            #pragma unroll
            for (int pp = 0; pp < 4; pp++) {
                float h = hv[pp];
                a[pp][0] += h * w0.x; a[pp][1] += h * w0.y;
                a[pp][2] += h * w0.z; a[pp][3] += h * w0.w;
                a[pp][4] += h * w1.x; a[pp][5] += h * w1.y;
                a[pp][6] += h * w1.z; a[pp][7] += h * w1.w;
                a[pp][8]  += h * w2.x; a[pp][9]  += h * w2.y;
                a[pp][10] += h * w2.z; a[pp][11] += h * w2.w;
            }
        }

        int j0 = jg * 4;
        #pragma unroll
        for (int pp = 0; pp < 4; pp++) {
            int p = pg * 4 + pp;
            int pglob = pbase + p;
            bool valid = (pglob < NP);
            int pc = valid ? pglob : NP - 1;
            float4 gxz = sgx4[p * 49 + jg];
            float4 gxr = sgx4[p * 49 + 16 + jg];
            float4 gxh = sgx4[p * 49 + 32 + jg];
            float z0 = sigm(gxz.x + a[pp][0]);
            float z1 = sigm(gxz.y + a[pp][1]);
            float z2 = sigm(gxz.z + a[pp][2]);
            float z3 = sigm(gxz.w + a[pp][3]);
            float r0 = sigm(gxr.x + a[pp][4]);
            float r1 = sigm(gxr.y + a[pp][5]);
            float r2 = sigm(gxr.z + a[pp][6]);
            float r3 = sigm(gxr.w + a[pp][7]);
            float c0 = tanh_fast(gxh.x + r0 * a[pp][8]);
            float c1 = tanh_fast(gxh.y + r1 * a[pp][9]);
            float c2 = tanh_fast(gxh.z + r2 * a[pp][10]);
            float c3 = tanh_fast(gxh.w + r3 * a[pp][11]);
            float h0 = shH[(j0 + 0) * 68 + p];
            float h1 = shH[(j0 + 1) * 68 + p];
            float h2 = shH[(j0 + 2) * 68 + p];
            float h3 = shH[(j0 + 3) * 68 + p];
            float n0 = z0 * h0 + (1.0f - z0) * c0;
            float n1 = z1 * h1 + (1.0f - z1) * c1;
            float n2 = z2 * h2 + (1.0f - z2) * c2;
            float n3 = z3 * h3 + (1.0f - z3) * c3;
            shHn[(j0 + 0) * 68 + p] = n0;
            shHn[(j0 + 1) * 68 + p] = n1;
            shHn[(j0 + 2) * 68 + p] = n2;
            shHn[(j0 + 3) * 68 + p] = n3;
            if (valid) {
                int li = l2p[pc * 8 + t];
                red4(g_m + (size_t)li * 64 + j0, n0, n1, n2, n3);
            }
        }
        hbuf ^= 1;
        __syncthreads();
    }

    // write path_state back
    float* shF = shh + hbuf * 4352;
    #pragma unroll
    for (int r = 0; r < 4; r++) {
        int idx = r * 256 + tid;
        int p = idx >> 4, iq = idx & 15;
        int pglob = pbase + p;
        if (pglob < NP) {
            float4 v;
            v.x = shF[(iq * 4 + 0) * 68 + p];
            v.y = shF[(iq * 4 + 1) * 68 + p];
            v.z = shF[(iq * 4 + 2) * 68 + p];
            v.w = shF[(iq * 4 + 3) * 68 + p];
            ((float4*)g_path)[(size_t)pglob * 16 + iq] = v;
        }
    }
}

// ---------------- edge MLP: link' = [node|link|m] @ We + be --------------
__global__ void __launch_bounds__(256) edge_kernel(const int* __restrict__ l2n,
                                                   int cur, int nxt) {
    __shared__ float sWe[4096];
    __shared__ float sbe[32];
    __shared__ float con[8][128];
    int tid = threadIdx.x;
    for (int i = tid; i < 4096; i += 256) sWe[i] = g_We[i];
    if (tid < 32) sbe[tid] = g_be[tid];
    int w = tid >> 5, lane = tid & 31;
    int l = blockIdx.x * 8 + w;
    int nn = l2n[l];
    con[w][lane]      = g_node[cur][(size_t)nn * 32 + lane];
    con[w][32 + lane] = g_link[cur][(size_t)l * 32 + lane];
    con[w][64 + lane] = g_m[(size_t)l * 64 + lane];
    con[w][96 + lane] = g_m[(size_t)l * 64 + 32 + lane];
    __syncthreads();
    float acc = sbe[lane];
    #pragma unroll
    for (int c = 0; c < 128; c++) acc += con[w][c] * sWe[c * 32 + lane];
    g_link[nxt][(size_t)l * 32 + lane] = acc;
}

// ---------------- ECC kernel-gen GEMM: [16 links x 512 outs]/block -------
__global__ void __launch_bounds__(256) ker_kernel(const float* __restrict__ wk,
                                                  const float* __restrict__ bk,
                                                  int lsel) {
    __shared__ __align__(16) float Ls[512];   // [c][l] : c 0..31, l 0..15
    int tid = threadIdx.x;
    int l0 = blockIdx.x * 16;
    const float* lst = g_link[lsel];
    for (int r = tid; r < 512; r += 256) {   // FIX: full 512-element stage
        int c = r >> 4, l = r & 15;
        Ls[r] = lst[(size_t)(l0 + l) * 32 + c];
    }
    __syncthreads();
    int o = blockIdx.y * 512 + tid;           // and o+256
    float acc0[16], acc1[16];
    float b0 = bk[o], b1 = bk[o + 256];
    #pragma unroll
    for (int l = 0; l < 16; l++) { acc0[l] = b0; acc1[l] = b1; }
    for (int c = 0; c < 32; c++) {
        float w0 = wk[c * 1024 + o];
        float w1 = wk[c * 1024 + o + 256];
        const float4* lp = (const float4*)(Ls + c * 16);
        #pragma unroll
        for (int q = 0; q < 4; q++) {
            float4 lv = lp[q];
            acc0[q * 4 + 0] += lv.x * w0; acc1[q * 4 + 0] += lv.x * w1;
            acc0[q * 4 + 1] += lv.y * w0; acc1[q * 4 + 1] += lv.y * w1;
            acc0[q * 4 + 2] += lv.z * w0; acc1[q * 4 + 2] += lv.z * w1;
            acc0[q * 4 + 3] += lv.w * w0; acc1[q * 4 + 3] += lv.w * w1;
        }
    }
    #pragma unroll
    for (int l = 0; l < 16; l++) {
        g_ker[(size_t)(l0 + l) * 1024 + o]       = acc0[l];
        g_ker[(size_t)(l0 + l) * 1024 + o + 256] = acc1[l];
    }
}

// ---------------- ECC message + aggregation ------------------------------
__global__ void __launch_bounds__(256) msg_kernel(const int* __restrict__ senders,
                                                  const int* __restrict__ recv,
                                                  int cur, int nxt) {
    __shared__ float sns[8][32];
    int tid = threadIdx.x, w = tid >> 5, lane = tid & 31;
    int l = blockIdx.x * 8 + w;
    int s = senders[l];
    sns[w][lane] = g_node[cur][(size_t)s * 32 + lane];
    __syncwarp();
    const float* kr = g_ker + (size_t)l * 1024 + lane;
    float acc = 0.0f;
    #pragma unroll
    for (int i = 0; i < 32; i++) acc += sns[w][i] * kr[i * 32];
    atomicAdd(&g_node[nxt][(size_t)recv[l] * 32 + lane], acc);
}

// ---------------- node root update ---------------------------------------
__global__ void __launch_bounds__(256) root_kernel(const float* __restrict__ wroot,
                                                   const float* __restrict__ broot,
                                                   int cur, int nxt) {
    __shared__ float sw[1024];
    int tid = threadIdx.x;
    for (int i = tid; i < 1024; i += 256) sw[i] = wroot[i];
    __syncthreads();
    int w = tid >> 5, lane = tid & 31;
    int n = blockIdx.x * 8 + w;
    const float* nr = g_node[cur] + (size_t)n * 32;
    float acc = broot[lane];
    #pragma unroll
    for (int i = 0; i < 32; i++) acc += nr[i] * sw[i * 32 + lane];
    g_node[nxt][(size_t)n * 32 + lane] += acc;
}

// ---------------- readout -------------------------------------------------
__global__ void __launch_bounds__(256) readout_kernel(
    const float* __restrict__ rw1, const float* __restrict__ rb1,
    const float* __restrict__ rw2, const float* __restrict__ rb2,
    const float* __restrict__ fw,  const float* __restrict__ fb,
    float* __restrict__ out) {
    __shared__ float sw1[2048], sw2[1024], sfw[96];
    __shared__ float shp[8][64], sr1[8][33];
    int tid = threadIdx.x, w = tid >> 5, lane = tid & 31;
    for (int i = tid; i < 2048; i += 256) sw1[i] = rw1[i];
    for (int i = tid; i < 1024; i += 256) sw2[i] = rw2[i];
    if (tid < 96) sfw[tid] = fw[tid];
    int p = blockIdx.x * 8 + w;
    shp[w][lane]      = g_path[(size_t)p * 64 + lane];
    shp[w][32 + lane] = g_path[(size_t)p * 64 + 32 + lane];
    __syncthreads();
    float acc = rb1[lane];
    #pragma unroll
    for (int i = 0; i < 64; i++) acc += shp[w][i] * sw1[i * 32 + lane];
    float r1 = selu_f(acc);
    sr1[w][lane] = r1;
    __syncwarp();
    float acc2 = rb2[lane];
    #pragma unroll
    for (int i = 0; i < 32; i++) acc2 += sr1[w][i] * sw2[i * 32 + lane];
    float r2 = selu_f(acc2);
    float part = r2 * sfw[lane] + shp[w][lane] * sfw[32 + lane]
               + shp[w][32 + lane] * sfw[64 + lane];
    #pragma unroll
    for (int o = 16; o; o >>= 1) part += __shfl_down_sync(0xffffffffu, part, o);
    if (lane == 0) out[p] = part + fb[0];
}

// ---------------------------- launcher ------------------------------------
extern "C" void kernel_launch(void* const* d_in, const int* in_sizes, int n_in,
                              void* d_out, int out_size) {
    const float* link_init = (const float*)d_in[0];
    const float* node_init = (const float*)d_in[1];
    const float* path_init = (const float*)d_in[2];
    const float* gru_wx    = (const float*)d_in[3];
    const float* gru_wh    = (const float*)d_in[4];
    const float* gru_b     = (const float*)d_in[5];
    const float* e_w1      = (const float*)d_in[6];
    const float* e_b1      = (const float*)d_in[7];
    const float* e_w2      = (const float*)d_in[8];
    const float* e_b2      = (const float*)d_in[9];
    const float* ecc_wk    = (const float*)d_in[10];
    const float* ecc_bk    = (const float*)d_in[11];
    const float* ecc_wroot = (const float*)d_in[12];
    const float* ecc_broot = (const float*)d_in[13];
    const float* r_w1      = (const float*)d_in[14];
    const float* r_b1      = (const float*)d_in[15];
    const float* r_w2      = (const float*)d_in[16];
    const float* r_b2      = (const float*)d_in[17];
    const float* f_w       = (const float*)d_in[18];
    const float* f_b       = (const float*)d_in[19];
    const int* l2p   = (const int*)d_in[22];
    const int* n2p   = (const int*)d_in[23];
    const int* l2n   = (const int*)d_in[24];
    const int* senders   = (const int*)d_in[25];
    const int* receivers = (const int*)d_in[26];
    float* out = (float*)d_out;

    cudaFuncSetAttribute(gru_kernel, cudaFuncAttributeMaxDynamicSharedMemorySize,
                         GRU_SMEM_BYTES);

    prep_gru_k<<<49, 256>>>(gru_wh, gru_b);
    prep_edge_k<<<17, 256>>>(e_w1, e_b1, e_w2, e_b2);
    init_link_k<<<2500, 256>>>(link_init);
    init_node_k<<<625, 256>>>(node_init);
    init_path_k<<<12500, 256>>>(path_init);

    int cur = 0;
    for (int it = 0; it < 2; it++) {
        int nxt = cur ^ 1;
        lx_kernel<<<2500, 192>>>(gru_wx, gru_b, cur);
        nx_kernel<<<625, 192>>>(gru_wx, cur);
        zero_m_k<<<1250, 256>>>();
        gru_kernel<<<782, 256, GRU_SMEM_BYTES>>>(l2p, n2p);
        edge_kernel<<<2500, 256>>>(l2n, cur, nxt);
        ker_kernel<<<dim3(1250, 2), 256>>>(ecc_wk, ecc_bk, nxt);
        zero_node_k<<<157, 256>>>(nxt);
        msg_kernel<<<2500, 256>>>(senders, receivers, cur, nxt);
        root_kernel<<<625, 256>>>(ecc_wroot, ecc_broot, cur, nxt);
        cur = nxt;
    }
    readout_kernel<<<6250, 256>>>(r_w1, r_b1, r_w2, r_b2, f_w, f_b, out);
}